// round 2
// baseline (speedup 1.0000x reference)
#include <cuda_runtime.h>
#include <cuda_bf16.h>

// Problem constants (EdgeConv_33930241638504): N=50000, E=800000, IN=OUT=16, T=8
#define MAXN 50048
#define IN_F 16
#define OUT_F 16
#define T_F 8
#define LN_EPS 1e-5f

// Scratch (device globals: allocation-free rule)
__device__ float g_g[MAXN * T_F * OUT_F];   // g[n][t][o], o fastest  (25.6 MB)
__device__ float g_c[MAXN * OUT_F];         // c[n][o]                (3.2 MB)
__device__ int   g_idx64;                   // 1 if edge_index is int64, 0 if int32

// ---------------------------------------------------------------------------
// Kernel 0: detect edge_index dtype.
// If int64 (little-endian, values < N): odd 32-bit words are all zero.
// If int32: odd words are random node ids -> essentially never all zero.
// ---------------------------------------------------------------------------
__global__ void detect_kernel(const unsigned int* __restrict__ idx_raw)
{
    int lane = threadIdx.x;  // 32 threads
    unsigned int any = 0;
    #pragma unroll
    for (int k = 0; k < 8; k++) {
        int i = lane * 8 + k;             // check odd words 1,3,...,511
        any |= idx_raw[2 * i + 1];
    }
    unsigned int ballot = __ballot_sync(0xffffffffu, any != 0);
    if (lane == 0) g_idx64 = (ballot == 0u) ? 1 : 0;
}

// ---------------------------------------------------------------------------
// Kernel 1: per-node preprocessing.
// 16 lanes per node; lane = o. Computes h = relu(LN(x)), then
//   g[n,t,o] = sum_i h[i] * w_edge[t, i*16+o]
//   c[n,o]   = sum_i h[i] * b_edge[i*16+o]
//   out[n,o] = sum_i h[i] * root[i*16+o] + bias[o]
// ---------------------------------------------------------------------------
__global__ __launch_bounds__(256) void node_kernel(
    const float* __restrict__ x,
    const float* __restrict__ ln_gamma,
    const float* __restrict__ ln_beta,
    const float* __restrict__ w_edge,   // [T, IN*OUT] = 2048 floats
    const float* __restrict__ b_edge,   // [IN*OUT]    = 256 floats
    const float* __restrict__ root,     // [IN, OUT]   = 256 floats
    const float* __restrict__ bias,     // [OUT]
    float* __restrict__ out,
    int N)
{
    __shared__ float Ws[T_F * IN_F * OUT_F];  // 2048
    __shared__ float Bs[IN_F * OUT_F];        // 256
    __shared__ float Rs[IN_F * OUT_F];        // 256

    for (int i = threadIdx.x; i < T_F * IN_F * OUT_F; i += blockDim.x) Ws[i] = w_edge[i];
    for (int i = threadIdx.x; i < IN_F * OUT_F; i += blockDim.x) { Bs[i] = b_edge[i]; Rs[i] = root[i]; }
    __syncthreads();

    int gtid = blockIdx.x * blockDim.x + threadIdx.x;
    int node = gtid >> 4;         // 16 lanes per node
    int o    = gtid & 15;
    bool valid = (node < N);
    int n = valid ? node : (N - 1);   // clamp loads; stores predicated

    float xv = x[n * IN_F + o];

    // LayerNorm stats over the 16-lane segment
    float s = xv;
    #pragma unroll
    for (int off = 8; off > 0; off >>= 1) s += __shfl_xor_sync(0xffffffffu, s, off, 16);
    float mu = s * (1.0f / 16.0f);
    float d = xv - mu;
    float v = d * d;
    #pragma unroll
    for (int off = 8; off > 0; off >>= 1) v += __shfl_xor_sync(0xffffffffu, v, off, 16);
    float var = v * (1.0f / 16.0f);
    float rstd = rsqrtf(var + LN_EPS);

    float h_own = d * rstd * ln_gamma[o] + ln_beta[o];
    h_own = fmaxf(h_own, 0.0f);   // ReLU

    float hv[IN_F];
    #pragma unroll
    for (int i = 0; i < IN_F; i++) hv[i] = __shfl_sync(0xffffffffu, h_own, i, 16);

    #pragma unroll
    for (int t = 0; t < T_F; t++) {
        float acc = 0.0f;
        #pragma unroll
        for (int i = 0; i < IN_F; i++) acc = fmaf(hv[i], Ws[t * 256 + i * 16 + o], acc);
        if (valid) g_g[((long)n) * 128 + t * 16 + o] = acc;
    }

    float cacc = 0.0f;
    #pragma unroll
    for (int i = 0; i < IN_F; i++) cacc = fmaf(hv[i], Bs[i * 16 + o], cacc);
    if (valid) g_c[n * OUT_F + o] = cacc;

    float bacc = bias[o];
    #pragma unroll
    for (int i = 0; i < IN_F; i++) bacc = fmaf(hv[i], Rs[i * 16 + o], bacc);
    if (valid) out[n * OUT_F + o] = bacc;
}

// ---------------------------------------------------------------------------
// Kernel 2: per-edge message + scatter.
// 4 lanes per edge; lane q owns outputs [4q, 4q+4).
//   msg[o] = c[src,o] + sum_t ea[t] * g[src,t,o]
//   red.add out[dst, 4q..4q+3]  (vectorized v4 reduction)
// ---------------------------------------------------------------------------
__global__ __launch_bounds__(256) void edge_kernel(
    const void* __restrict__ edge_index,       // [2, E] int64 OR int32 (see g_idx64)
    const float* __restrict__ edge_attr,       // [E, 8]
    float* __restrict__ out,
    int E)
{
    int tid = blockIdx.x * blockDim.x + threadIdx.x;
    int e = tid >> 2;
    int q = tid & 3;
    if (e >= E) return;

    int src, dst;
    if (g_idx64) {
        const long long* ei = (const long long*)edge_index;
        src = (int)ei[e];
        dst = (int)ei[(long)E + e];
    } else {
        const int* ei = (const int*)edge_index;
        src = ei[e];
        dst = ei[E + e];
    }

    // edge attributes (8 floats; same addr within quad -> L1 broadcast)
    const float4* eap = (const float4*)(edge_attr + (long)e * T_F);
    float4 ea0 = eap[0];
    float4 ea1 = eap[1];
    float eat[T_F] = {ea0.x, ea0.y, ea0.z, ea0.w, ea1.x, ea1.y, ea1.z, ea1.w};

    // start from c[src]
    const float4* c4 = (const float4*)g_c;
    float4 m = c4[src * 4 + q];

    // accumulate over t: g[src, t, 4q..4q+3]
    const float4* g4 = (const float4*)g_g + (long)src * 32 + q;
    #pragma unroll
    for (int t = 0; t < T_F; t++) {
        float4 gv = g4[t * 4];
        float a = eat[t];
        m.x = fmaf(a, gv.x, m.x);
        m.y = fmaf(a, gv.y, m.y);
        m.z = fmaf(a, gv.z, m.z);
        m.w = fmaf(a, gv.w, m.w);
    }

    // vectorized global reduction into out[dst, 4q..4q+3]
    float* dstp = out + (long)dst * OUT_F + q * 4;
    asm volatile("red.global.add.v4.f32 [%0], {%1, %2, %3, %4};"
                 :: "l"(dstp), "f"(m.x), "f"(m.y), "f"(m.z), "f"(m.w)
                 : "memory");
}

// ---------------------------------------------------------------------------
extern "C" void kernel_launch(void* const* d_in, const int* in_sizes, int n_in,
                              void* d_out, int out_size)
{
    const float* x        = (const float*)d_in[0];
    const void*  eidx     = d_in[1];
    const float* eattr    = (const float*)d_in[2];
    const float* ln_gamma = (const float*)d_in[3];
    const float* ln_beta  = (const float*)d_in[4];
    const float* w_edge   = (const float*)d_in[5];
    const float* b_edge   = (const float*)d_in[6];
    const float* root     = (const float*)d_in[7];
    const float* bias     = (const float*)d_in[8];
    float* out = (float*)d_out;

    int N = in_sizes[0] / IN_F;
    int E = in_sizes[1] / 2;

    detect_kernel<<<1, 32>>>((const unsigned int*)eidx);

    {
        int threads = N * 16;
        int block = 256;
        int grid = (threads + block - 1) / block;
        node_kernel<<<grid, block>>>(x, ln_gamma, ln_beta, w_edge, b_edge, root, bias, out, N);
    }
    {
        int threads = E * 4;
        int block = 256;
        int grid = (threads + block - 1) / block;
        edge_kernel<<<grid, block>>>(eidx, eattr, out, E);
    }
}

// round 3
// speedup vs baseline: 1.0036x; 1.0036x over previous
#include <cuda_runtime.h>
#include <cuda_bf16.h>
#include <cuda_fp16.h>

// Problem constants (EdgeConv_33930241638504): N=50000, E=800000, IN=OUT=16, T=8
#define MAXN 50048
#define IN_F 16
#define OUT_F 16
#define T_F 8
#define LN_EPS 1e-5f

// Scratch (device globals: allocation-free rule)
// g stored fp16, layout [n][q][t][4]: lane q's 8 t-steps x 4 outputs contiguous (64B)
__device__ __half g_gh[MAXN * T_F * OUT_F];   // 12.8 MB
__device__ float  g_c[MAXN * OUT_F];          // c[n][o] fp32 (3.2 MB)
__device__ int    g_idx64;                    // 1 if edge_index is int64, 0 if int32

// ---------------------------------------------------------------------------
// Kernel 1: per-node preprocessing (+ inline edge_index dtype detection).
// 16 lanes per node; lane = o. Computes h = relu(LN(x)), then
//   g[n,t,o] = sum_i h[i] * w_edge[t, i*16+o]      (stored fp16, [n][q][t][4])
//   c[n,o]   = sum_i h[i] * b_edge[i*16+o]
//   out[n,o] = sum_i h[i] * root[i*16+o] + bias[o]
// ---------------------------------------------------------------------------
__global__ __launch_bounds__(256) void node_kernel(
    const float* __restrict__ x,
    const float* __restrict__ ln_gamma,
    const float* __restrict__ ln_beta,
    const float* __restrict__ w_edge,   // [T, IN*OUT] = 2048 floats
    const float* __restrict__ b_edge,   // [IN*OUT]
    const float* __restrict__ root,     // [IN, OUT]
    const float* __restrict__ bias,     // [OUT]
    const unsigned int* __restrict__ idx_raw,  // for dtype detection
    float* __restrict__ out,
    int N)
{
    __shared__ float Ws[T_F * IN_F * OUT_F];  // 2048
    __shared__ float Bs[IN_F * OUT_F];        // 256
    __shared__ float Rs[IN_F * OUT_F];        // 256

    for (int i = threadIdx.x; i < T_F * IN_F * OUT_F; i += blockDim.x) Ws[i] = w_edge[i];
    for (int i = threadIdx.x; i < IN_F * OUT_F; i += blockDim.x) { Bs[i] = b_edge[i]; Rs[i] = root[i]; }

    // dtype detection, folded in (block 0, warp 0). int64 little-endian with
    // values < N => odd 32-bit words all zero; int32 => effectively never.
    if (blockIdx.x == 0 && threadIdx.x < 32) {
        int lane = threadIdx.x;
        unsigned int any = 0;
        #pragma unroll
        for (int k = 0; k < 8; k++) any |= idx_raw[2 * (lane * 8 + k) + 1];
        unsigned int ballot = __ballot_sync(0xffffffffu, any != 0);
        if (lane == 0) g_idx64 = (ballot == 0u) ? 1 : 0;
    }
    __syncthreads();

    int gtid = blockIdx.x * blockDim.x + threadIdx.x;
    int node = gtid >> 4;         // 16 lanes per node
    int o    = gtid & 15;
    bool valid = (node < N);
    int n = valid ? node : (N - 1);   // clamp loads; stores predicated

    float xv = x[n * IN_F + o];

    // LayerNorm stats over the 16-lane segment
    float s = xv;
    #pragma unroll
    for (int off = 8; off > 0; off >>= 1) s += __shfl_xor_sync(0xffffffffu, s, off, 16);
    float mu = s * (1.0f / 16.0f);
    float d = xv - mu;
    float v = d * d;
    #pragma unroll
    for (int off = 8; off > 0; off >>= 1) v += __shfl_xor_sync(0xffffffffu, v, off, 16);
    float var = v * (1.0f / 16.0f);
    float rstd = rsqrtf(var + LN_EPS);

    float h_own = d * rstd * ln_gamma[o] + ln_beta[o];
    h_own = fmaxf(h_own, 0.0f);   // ReLU

    float hv[IN_F];
    #pragma unroll
    for (int i = 0; i < IN_F; i++) hv[i] = __shfl_sync(0xffffffffu, h_own, i, 16);

    // g[n,t,o] -> fp16, layout [n][q=o/4][t][o%4]
    int q  = o >> 2;
    int o4 = o & 3;
    #pragma unroll
    for (int t = 0; t < T_F; t++) {
        float acc = 0.0f;
        #pragma unroll
        for (int i = 0; i < IN_F; i++) acc = fmaf(hv[i], Ws[t * 256 + i * 16 + o], acc);
        if (valid) g_gh[((long)n) * 128 + q * 32 + t * 4 + o4] = __float2half(acc);
    }

    float cacc = 0.0f;
    #pragma unroll
    for (int i = 0; i < IN_F; i++) cacc = fmaf(hv[i], Bs[i * 16 + o], cacc);
    if (valid) g_c[n * OUT_F + o] = cacc;

    float bacc = bias[o];
    #pragma unroll
    for (int i = 0; i < IN_F; i++) bacc = fmaf(hv[i], Rs[i * 16 + o], bacc);
    if (valid) out[n * OUT_F + o] = bacc;
}

// ---------------------------------------------------------------------------
// Kernel 2: per-edge message + scatter.
// 4 lanes per edge; lane q owns outputs [4q, 4q+4).
//   msg[o] = c[src,o] + sum_t ea[t] * g[src,t,o]
//   red.add out[dst, 4q..4q+3]  (vectorized v4 reduction)
// g gather: 4x LDG.128 of fp16 (64B per lane), c: 1x LDG.128 fp32.
// ---------------------------------------------------------------------------
__global__ __launch_bounds__(256) void edge_kernel(
    const void* __restrict__ edge_index,       // [2, E] int64 OR int32 (see g_idx64)
    const float* __restrict__ edge_attr,       // [E, 8]
    float* __restrict__ out,
    int E)
{
    int tid = blockIdx.x * blockDim.x + threadIdx.x;
    int e = tid >> 2;
    int q = tid & 3;
    if (e >= E) return;

    int src, dst;
    if (g_idx64) {
        const long long* ei = (const long long*)edge_index;
        src = (int)ei[e];
        dst = (int)ei[(long)E + e];
    } else {
        const int* ei = (const int*)edge_index;
        src = ei[e];
        dst = ei[E + e];
    }

    // edge attributes (same addr within quad -> L1 broadcast)
    const float4* eap = (const float4*)(edge_attr + (long)e * T_F);
    float4 ea0 = eap[0];
    float4 ea1 = eap[1];
    float eat[T_F] = {ea0.x, ea0.y, ea0.z, ea0.w, ea1.x, ea1.y, ea1.z, ea1.w};

    // start from c[src] (fp32)
    const float4* c4 = (const float4*)g_c;
    float4 m = c4[src * 4 + q];

    // g[src] fp16: lane's 64B block = [t=0..7][4 outputs]
    const uint4* g4 = (const uint4*)(g_gh + (long)src * 128 + q * 32);
    #pragma unroll
    for (int j = 0; j < 4; j++) {
        uint4 u = g4[j];                      // t = 2j (x,y) and t = 2j+1 (z,w)
        float a0 = eat[2 * j];
        float a1 = eat[2 * j + 1];
        float2 p;
        p = __half22float2(*(const __half2*)&u.x);
        m.x = fmaf(a0, p.x, m.x); m.y = fmaf(a0, p.y, m.y);
        p = __half22float2(*(const __half2*)&u.y);
        m.z = fmaf(a0, p.x, m.z); m.w = fmaf(a0, p.y, m.w);
        p = __half22float2(*(const __half2*)&u.z);
        m.x = fmaf(a1, p.x, m.x); m.y = fmaf(a1, p.y, m.y);
        p = __half22float2(*(const __half2*)&u.w);
        m.z = fmaf(a1, p.x, m.z); m.w = fmaf(a1, p.y, m.w);
    }

    // vectorized global reduction into out[dst, 4q..4q+3]
    float* dstp = out + (long)dst * OUT_F + q * 4;
    asm volatile("red.global.add.v4.f32 [%0], {%1, %2, %3, %4};"
                 :: "l"(dstp), "f"(m.x), "f"(m.y), "f"(m.z), "f"(m.w)
                 : "memory");
}

// ---------------------------------------------------------------------------
extern "C" void kernel_launch(void* const* d_in, const int* in_sizes, int n_in,
                              void* d_out, int out_size)
{
    const float* x        = (const float*)d_in[0];
    const void*  eidx     = d_in[1];
    const float* eattr    = (const float*)d_in[2];
    const float* ln_gamma = (const float*)d_in[3];
    const float* ln_beta  = (const float*)d_in[4];
    const float* w_edge   = (const float*)d_in[5];
    const float* b_edge   = (const float*)d_in[6];
    const float* root     = (const float*)d_in[7];
    const float* bias     = (const float*)d_in[8];
    float* out = (float*)d_out;

    int N = in_sizes[0] / IN_F;
    int E = in_sizes[1] / 2;

    {
        int threads = N * 16;
        int block = 256;
        int grid = (threads + block - 1) / block;
        node_kernel<<<grid, block>>>(x, ln_gamma, ln_beta, w_edge, b_edge, root, bias,
                                     (const unsigned int*)eidx, out, N);
    }
    {
        int threads = E * 4;
        int block = 256;
        int grid = (threads + block - 1) / block;
        edge_kernel<<<grid, block>>>(eidx, eattr, out, E);
    }
}

// round 5
// speedup vs baseline: 1.1967x; 1.1924x over previous
#include <cuda_runtime.h>
#include <cuda_bf16.h>
#include <cuda_fp16.h>

// Problem constants (EdgeConv_33930241638504): N=50000, E=800000, IN=OUT=16, T=8
#define MAXN 50048
#define IN_F 16
#define OUT_F 16
#define T_F 8
#define LN_EPS 1e-5f

// Scratch (device globals: allocation-free rule)
// g fp16, layout [n][j=t/2][o][s=t&1]: half index = n*128 + j*32 + o*2 + s.
// Quad lane q reads chunk (j, o=4q..4q+3): 16B at j*32 + q*8 -> the quad's 4
// loads per j cover contiguous 64B => minimal L1 wavefronts.
__device__ __half g_gh[MAXN * T_F * OUT_F];   // 12.8 MB
__device__ float  g_c[MAXN * OUT_F];          // c[n][o] fp32 (3.2 MB)
__device__ int    g_idx64;                    // 1 if edge_index is int64, 0 if int32

// ---------------------------------------------------------------------------
// Kernel 1: per-node preprocessing (+ inline edge_index dtype detection).
// 16 lanes per node; lane = o. h = relu(LN(x));
//   g[n,t,o] = sum_i h[i]*W[t,i*16+o]  (fp16, staged via smem -> 1 STG.128/thr)
//   c[n,o]   = sum_i h[i]*b_edge[i*16+o]
//   out[n,o] = sum_i h[i]*root[i*16+o] + bias[o]
// ---------------------------------------------------------------------------
__global__ __launch_bounds__(256) void node_kernel(
    const float* __restrict__ x,
    const float* __restrict__ ln_gamma,
    const float* __restrict__ ln_beta,
    const float* __restrict__ w_edge,   // [T, IN*OUT] = 2048 floats
    const float* __restrict__ b_edge,   // [IN*OUT]
    const float* __restrict__ root,     // [IN, OUT]
    const float* __restrict__ bias,     // [OUT]
    const unsigned int* __restrict__ idx_raw,  // for dtype detection
    float* __restrict__ out,
    int N)
{
    __shared__ float Ws[T_F * IN_F * OUT_F];  // 2048
    __shared__ float Bs[IN_F * OUT_F];        // 256
    __shared__ float Rs[IN_F * OUT_F];        // 256
    __shared__ __half Gs[8 * 256];            // 8 warps x (2 nodes x 128 halves)

    for (int i = threadIdx.x; i < T_F * IN_F * OUT_F; i += blockDim.x) Ws[i] = w_edge[i];
    for (int i = threadIdx.x; i < IN_F * OUT_F; i += blockDim.x) { Bs[i] = b_edge[i]; Rs[i] = root[i]; }

    // dtype detection (block 0, warp 0): int64 LE with values < N => odd words zero.
    if (blockIdx.x == 0 && threadIdx.x < 32) {
        int lane = threadIdx.x;
        unsigned int any = 0;
        #pragma unroll
        for (int k = 0; k < 8; k++) any |= idx_raw[2 * (lane * 8 + k) + 1];
        unsigned int ballot = __ballot_sync(0xffffffffu, any != 0);
        if (lane == 0) g_idx64 = (ballot == 0u) ? 1 : 0;
    }
    __syncthreads();

    int gtid = blockIdx.x * blockDim.x + threadIdx.x;
    int node = gtid >> 4;         // 16 lanes per node
    int o    = gtid & 15;
    bool valid = (node < N);
    int n = valid ? node : (N - 1);   // clamp loads; stores predicated

    float xv = x[n * IN_F + o];

    // LayerNorm stats over the 16-lane segment
    float s = xv;
    #pragma unroll
    for (int off = 8; off > 0; off >>= 1) s += __shfl_xor_sync(0xffffffffu, s, off, 16);
    float mu = s * (1.0f / 16.0f);
    float d = xv - mu;
    float v = d * d;
    #pragma unroll
    for (int off = 8; off > 0; off >>= 1) v += __shfl_xor_sync(0xffffffffu, v, off, 16);
    float var = v * (1.0f / 16.0f);
    float rstd = rsqrtf(var + LN_EPS);

    float h_own = d * rstd * ln_gamma[o] + ln_beta[o];
    h_own = fmaxf(h_own, 0.0f);   // ReLU

    float hv[IN_F];
    #pragma unroll
    for (int i = 0; i < IN_F; i++) hv[i] = __shfl_sync(0xffffffffu, h_own, i, 16);

    // g[n,t,o]: stage into smem at [warp][local_node*128 + (t>>1)*32 + o*2 + (t&1)]
    int warp = threadIdx.x >> 5;
    int lane = threadIdx.x & 31;
    int local_node = (threadIdx.x >> 4) & 1;  // which of the warp's 2 nodes
    __half* gw = Gs + warp * 256;
    #pragma unroll
    for (int t = 0; t < T_F; t++) {
        float acc = 0.0f;
        #pragma unroll
        for (int i = 0; i < IN_F; i++) acc = fmaf(hv[i], Ws[t * 256 + i * 16 + o], acc);
        gw[local_node * 128 + (t >> 1) * 32 + o * 2 + (t & 1)] = __float2half(acc);
    }
    __syncwarp();

    // vectorized write-out: lane l stores 16B (8 halves) at g_gh[first_node*128 + l*8].
    // Lane l covers node first_node + (l>>4); predicate on that node being valid.
    int first_node = (blockIdx.x * (blockDim.x >> 4)) + warp * 2;  // warp's node0
    int covered = first_node + (lane >> 4);
    if (covered < N) {
        uint4 sv = ((const uint4*)gw)[lane];
        *((uint4*)(g_gh + (long)first_node * 128 + lane * 8)) = sv;
    }

    float cacc = 0.0f;
    #pragma unroll
    for (int i = 0; i < IN_F; i++) cacc = fmaf(hv[i], Bs[i * 16 + o], cacc);
    if (valid) g_c[n * OUT_F + o] = cacc;

    float bacc = bias[o];
    #pragma unroll
    for (int i = 0; i < IN_F; i++) bacc = fmaf(hv[i], Rs[i * 16 + o], bacc);
    if (valid) out[n * OUT_F + o] = bacc;
}

// ---------------------------------------------------------------------------
// Kernel 2: per-edge message + scatter.
// 4 lanes per edge; lane q owns outputs [4q, 4q+4).
//   msg[o] = c[src,o] + sum_t ea[t]*g[src,t,o]
// g gather: 4x LDG.128; for each j the quad reads contiguous 64B (half a line).
// ---------------------------------------------------------------------------
__global__ __launch_bounds__(256) void edge_kernel(
    const void* __restrict__ edge_index,       // [2, E] int64 OR int32 (see g_idx64)
    const float* __restrict__ edge_attr,       // [E, 8]
    float* __restrict__ out,
    int E)
{
    int tid = blockIdx.x * blockDim.x + threadIdx.x;
    int e = tid >> 2;
    int q = tid & 3;
    if (e >= E) return;

    int src, dst;
    if (g_idx64) {
        const long long* ei = (const long long*)edge_index;
        src = (int)ei[e];
        dst = (int)ei[(long)E + e];
    } else {
        const int* ei = (const int*)edge_index;
        src = ei[e];
        dst = ei[E + e];
    }

    // edge attributes (same addr within quad -> broadcast)
    const float4* eap = (const float4*)(edge_attr + (long)e * T_F);
    float4 ea0 = eap[0];
    float4 ea1 = eap[1];
    float eat[T_F] = {ea0.x, ea0.y, ea0.z, ea0.w, ea1.x, ea1.y, ea1.z, ea1.w};

    // start from c[src] (fp32)
    const float4* c4 = (const float4*)g_c;
    float4 m = c4[src * 4 + q];

    // g[src]: chunk j at uint4 index j*4 + q; u.{x,y,z,w} = half2 {t=2j, t=2j+1}
    // for outputs 4q..4q+3.
    const uint4* g4 = (const uint4*)(g_gh + (long)src * 128);
    #pragma unroll
    for (int j = 0; j < 4; j++) {
        uint4 u = g4[j * 4 + q];
        float a0 = eat[2 * j];
        float a1 = eat[2 * j + 1];
        float2 p;
        p = __half22float2(*(const __half2*)&u.x);
        m.x = fmaf(a0, p.x, fmaf(a1, p.y, m.x));
        p = __half22float2(*(const __half2*)&u.y);
        m.y = fmaf(a0, p.x, fmaf(a1, p.y, m.y));
        p = __half22float2(*(const __half2*)&u.z);
        m.z = fmaf(a0, p.x, fmaf(a1, p.y, m.z));
        p = __half22float2(*(const __half2*)&u.w);
        m.w = fmaf(a0, p.x, fmaf(a1, p.y, m.w));
    }

    // vectorized global reduction into out[dst, 4q..4q+3]
    float* dstp = out + (long)dst * OUT_F + q * 4;
    asm volatile("red.global.add.v4.f32 [%0], {%1, %2, %3, %4};"
                 :: "l"(dstp), "f"(m.x), "f"(m.y), "f"(m.z), "f"(m.w)
                 : "memory");
}

// ---------------------------------------------------------------------------
extern "C" void kernel_launch(void* const* d_in, const int* in_sizes, int n_in,
                              void* d_out, int out_size)
{
    const float* x        = (const float*)d_in[0];
    const void*  eidx     = d_in[1];
    const float* eattr    = (const float*)d_in[2];
    const float* ln_gamma = (const float*)d_in[3];
    const float* ln_beta  = (const float*)d_in[4];
    const float* w_edge   = (const float*)d_in[5];
    const float* b_edge   = (const float*)d_in[6];
    const float* root     = (const float*)d_in[7];
    const float* bias     = (const float*)d_in[8];
    float* out = (float*)d_out;

    int N = in_sizes[0] / IN_F;
    int E = in_sizes[1] / 2;

    {
        int threads = N * 16;
        int block = 256;
        int grid = (threads + block - 1) / block;
        node_kernel<<<grid, block>>>(x, ln_gamma, ln_beta, w_edge, b_edge, root, bias,
                                     (const unsigned int*)eidx, out, N);
    }
    {
        int threads = E * 4;
        int block = 256;
        int grid = (threads + block - 1) / block;
        edge_kernel<<<grid, block>>>(eidx, eattr, out, E);
    }
}